// round 3
// baseline (speedup 1.0000x reference)
#include <cuda_runtime.h>
#include <math.h>
#include <stdint.h>

#define NB 4
#define NS 2048
#define ND 1024
#define NH 16
#define NHD 64
#define NTOK (NB*NS)

// Scratch (device globals: allocation-free)
__device__ float g_Q[(size_t)NB*NH*NS*NHD];
__device__ float g_K[(size_t)NB*NH*NS*NHD];
__device__ float g_V[(size_t)NB*NH*NS*NHD];
__device__ float g_AO[(size_t)NTOK*ND];

__device__ __forceinline__ float tf32r(float x){
    uint32_t y;
    asm("cvt.rna.tf32.f32 %0, %1;" : "=r"(y) : "f"(x));
    return __uint_as_float(y);
}

__device__ __forceinline__ void mma8(float c[4], const float a[4], const float b[2]){
    asm volatile(
      "mma.sync.aligned.m16n8k8.row.col.f32.tf32.tf32.f32 "
      "{%0,%1,%2,%3}, {%4,%5,%6,%7}, {%8,%9}, {%0,%1,%2,%3};\n"
      : "+f"(c[0]),"+f"(c[1]),"+f"(c[2]),"+f"(c[3])
      : "r"(__float_as_uint(a[0])),"r"(__float_as_uint(a[1])),
        "r"(__float_as_uint(a[2])),"r"(__float_as_uint(a[3])),
        "r"(__float_as_uint(b[0])),"r"(__float_as_uint(b[1])));
}

// ---------------------------------------------------------------------------
// Kernel 1: QKV projection (tf32x2 split for q/k, plain tf32 for v)
// Paired smem layout: [row][kchunk][slot] float4 {hi(c), lo(c), hi(c+4), lo(c+4)}
// row stride 20 float4-units (== 4 mod 8 -> conflict-free LDS.128 frag reads)
// ---------------------------------------------------------------------------
__global__ __launch_bounds__(128) void qkv_kernel(
    const float* __restrict__ X,
    const float* __restrict__ wq, const float* __restrict__ wk, const float* __restrict__ wv,
    const float* __restrict__ cosp, const float* __restrict__ sinp,
    const float* __restrict__ qsc, const float* __restrict__ ksc)
{
    __shared__ float4 Ap4[64*20];
    __shared__ float4 Bp4[64*20];

    const int tid = threadIdx.x;
    const int lane = tid & 31, warp = tid >> 5;
    const int wm = warp >> 1, wn = warp & 1;
    const int lg = lane >> 2, tg = lane & 3;
    // staging lane mapping: s fastest -> conflict-free STS.128
    const int s_ = tid & 3, ch_ = (tid >> 2) & 3, r0_ = tid >> 4;

    const int tok0 = blockIdx.x * 64;
    const int which = blockIdx.y >> 4, head = blockIdx.y & 15;
    const bool split = (which != 2);
    const float* W = (which==0) ? wq : (which==1) ? wk : wv;
    const float* Wb = W + (size_t)head * 64 * ND;
    const float* Xb = X + (size_t)tok0 * ND;

    float c[2][4][4];
    #pragma unroll
    for (int mi=0;mi<2;mi++)
      #pragma unroll
      for (int ni=0;ni<4;ni++)
        #pragma unroll
        for (int q=0;q<4;q++) c[mi][ni][q]=0.f;

    for (int kt = 0; kt < ND/32; ++kt){
        const int k0 = kt * 32;
        __syncthreads();
        const float* Xa = Xb + k0 + ch_*8 + s_;
        const float* Wa = Wb + k0 + ch_*8 + s_;
        #pragma unroll
        for (int rr=0; rr<8; rr++){
            int row = rr*8 + r0_;
            float va = Xa[(size_t)row*ND], vb = Xa[(size_t)row*ND + 4];
            float ha = tf32r(va), hb = tf32r(vb);
            Ap4[row*20 + ch_*4 + s_] = make_float4(ha, tf32r(va-ha), hb, tf32r(vb-hb));
            float wa = Wa[(size_t)row*ND], wb2 = Wa[(size_t)row*ND + 4];
            float hwa = tf32r(wa), hwb = tf32r(wb2);
            Bp4[row*20 + ch_*4 + s_] = make_float4(hwa, tf32r(wa-hwa), hwb, tf32r(wb2-hwb));
        }
        __syncthreads();
        #pragma unroll
        for (int ks=0;ks<4;ks++){
            float ah[2][4], al[2][4], bh[4][2], bl[4][2];
            #pragma unroll
            for (int mi=0;mi<2;mi++){
                int rb = wm*32 + mi*16;
                float4 f0 = Ap4[(rb+lg)*20 + ks*4 + tg];
                float4 f1 = Ap4[(rb+8+lg)*20 + ks*4 + tg];
                ah[mi][0]=f0.x; ah[mi][1]=f1.x; ah[mi][2]=f0.z; ah[mi][3]=f1.z;
                al[mi][0]=f0.y; al[mi][1]=f1.y; al[mi][2]=f0.w; al[mi][3]=f1.w;
            }
            #pragma unroll
            for (int ni=0;ni<4;ni++){
                int n2 = wn*32 + ni*8;
                float4 f = Bp4[(n2+lg)*20 + ks*4 + tg];
                bh[ni][0]=f.x; bh[ni][1]=f.z;
                bl[ni][0]=f.y; bl[ni][1]=f.w;
            }
            #pragma unroll
            for (int mi=0;mi<2;mi++)
              #pragma unroll
              for (int ni=0;ni<4;ni++)
                mma8(c[mi][ni], ah[mi], bh[ni]);
            if (split){
                #pragma unroll
                for (int mi=0;mi<2;mi++)
                  #pragma unroll
                  for (int ni=0;ni<4;ni++){
                    mma8(c[mi][ni], ah[mi], bl[ni]);
                    mma8(c[mi][ni], al[mi], bh[ni]);
                  }
            }
        }
    }
    __syncthreads();
    // Stage tile for row-wise epilogue (overlay smem: 64*65 floats < Ap4)
    float* smf = (float*)Ap4;
    float (*Ct)[65] = (float(*)[65])smf;
    #pragma unroll
    for (int mi=0;mi<2;mi++)
      #pragma unroll
      for (int ni=0;ni<4;ni++){
        int row = wm*32+mi*16+lg;
        int col = wn*32+ni*8+2*tg;
        Ct[row][col]     = c[mi][ni][0];
        Ct[row][col+1]   = c[mi][ni][1];
        Ct[row+8][col]   = c[mi][ni][2];
        Ct[row+8][col+1] = c[mi][ni][3];
      }
    __syncthreads();
    if (tid < 64){
        int r = tid;
        int token = tok0 + r;
        int bb = token >> 11, s = token & (NS-1);
        float ssum = 0.f;
        #pragma unroll
        for (int d=0; d<64; d++){ float x = Ct[r][d]; ssum += x*x; }
        float rms = rsqrtf(ssum * (1.f/64.f) + 1e-6f);
        float* op = ((which==0)? g_Q : (which==1)? g_K : g_V)
                    + ((size_t)((bb*NH + head)*NS + s))*NHD;
        if (which == 2){
            #pragma unroll 8
            for (int d=0; d<64; d++) op[d] = Ct[r][d]*rms;
        } else {
            const float* sc = (which==0)? qsc : ksc;
            const float* cb = cosp + (size_t)token*NHD;
            const float* sb = sinp + (size_t)token*NHD;
            #pragma unroll 8
            for (int d=0; d<64; d++){
                int j = d & 31;
                float x  = Ct[r][d]*rms*sc[d];
                int pd = (j<16)? d+16 : d-16;
                float xp = Ct[r][pd]*rms*sc[pd];
                float rot = (j<16)? -xp : xp;
                op[d] = x*cb[d] + rot*sb[d];
            }
        }
    }
}

// ---------------------------------------------------------------------------
// Kernel 2: flash attention. Block = 128 q rows, 8 warps x 16 rows.
// K tile in paired float4 layout (1 LDS.128 -> 3 QK mmas).
// P staged as paired float2. V row-major scalar b-frags.
// ---------------------------------------------------------------------------
#define KP4_ELEMS (64*36)          // float4 units (36/row, stride==4 mod 8)
#define VS_OFF    (KP4_ELEMS*16)   // bytes
#define PS_OFF    (VS_OFF + 64*68*4)
#define ATTN_SMEM (PS_OFF + 128*72*4)

__global__ __launch_bounds__(256) void attn_kernel()
{
    extern __shared__ char dsm[];
    float4* Kp4 = (float4*)dsm;
    float*  Vs  = (float*)(dsm + VS_OFF);   // [64][68]
    float*  Psf = (float*)(dsm + PS_OFF);   // [128][72] paired float2 layout

    const int tid = threadIdx.x, lane = tid&31, w = tid>>5;
    const int lg = lane>>2, tg = lane&3;
    const int s_ = tid & 3, ch_ = (tid >> 2) & 7, r0_ = tid >> 5;  // staging map
    const int qt = blockIdx.x, h = blockIdx.y, b = blockIdx.z;
    const size_t hb = ((size_t)(b*NH + h))*NS*NHD;

    // ---- stage Q (two 64-row halves through Kp4), build register frags ----
    float qh[8][4], ql[8][4];
    const float* Qp = g_Q + hb + (size_t)qt*128*NHD;
    #pragma unroll
    for (int half=0; half<2; half++){
        const float* Qh = Qp + half*64*NHD + ch_*8 + s_;
        #pragma unroll
        for (int rr=0; rr<8; rr++){
            int row = rr*8 + r0_;
            float va = Qh[row*64], vb = Qh[row*64 + 4];
            float ha = tf32r(va), hv = tf32r(vb);
            Kp4[row*36 + ch_*4 + s_] = make_float4(ha, tf32r(va-ha), hv, tf32r(vb-hv));
        }
        __syncthreads();
        if ((w>>2) == half){
            int rb = (w&3)*16;
            #pragma unroll
            for (int ks=0;ks<8;ks++){
                float4 f0 = Kp4[(rb+lg)*36 + ks*4 + tg];
                float4 f1 = Kp4[(rb+8+lg)*36 + ks*4 + tg];
                qh[ks][0]=f0.x; qh[ks][1]=f1.x; qh[ks][2]=f0.z; qh[ks][3]=f1.z;
                ql[ks][0]=f0.y; ql[ks][1]=f1.y; ql[ks][2]=f0.w; ql[ks][3]=f1.w;
            }
        }
        __syncthreads();
    }

    float ofr[8][4];
    #pragma unroll
    for (int ni=0;ni<8;ni++){ ofr[ni][0]=0;ofr[ni][1]=0;ofr[ni][2]=0;ofr[ni][3]=0; }
    float m0=-INFINITY, m1=-INFINITY, l0=0.f, l1=0.f;

    const int prow = w*16 + lg;

    for (int kt=0; kt<NS/64; ++kt){
        const float* Kp = g_K + hb + (size_t)kt*64*NHD;
        const float* Vp = g_V + hb + (size_t)kt*64*NHD;
        // stage K in paired layout
        {
            const float* gp = Kp + ch_*8 + s_;
            #pragma unroll
            for (int rr=0; rr<8; rr++){
                int row = rr*8 + r0_;
                float va = gp[row*64], vb = gp[row*64 + 4];
                float ha = tf32r(va), hv = tf32r(vb);
                Kp4[row*36 + ch_*4 + s_] = make_float4(ha, tf32r(va-ha), hv, tf32r(vb-hv));
            }
        }
        // stage V (row-major, tf32)
        #pragma unroll
        for (int i=0;i<4;i++){
            int idx = tid + i*256, row = idx>>4, c4 = idx&15;
            float4 vv = *(const float4*)(Vp + (size_t)row*64 + c4*4);
            Vs[row*68 + c4*4+0]=tf32r(vv.x); Vs[row*68 + c4*4+1]=tf32r(vv.y);
            Vs[row*68 + c4*4+2]=tf32r(vv.z); Vs[row*68 + c4*4+3]=tf32r(vv.w);
        }
        __syncthreads();

        // ---- QK^T (tf32x2): 1 LDS.128 per 3 mmas ----
        float sfr[8][4];
        #pragma unroll
        for (int ni=0;ni<8;ni++){ sfr[ni][0]=0;sfr[ni][1]=0;sfr[ni][2]=0;sfr[ni][3]=0; }
        #pragma unroll
        for (int ni=0;ni<8;ni++){
            #pragma unroll
            for (int ks=0;ks<8;ks++){
                float4 f = Kp4[(ni*8+lg)*36 + ks*4 + tg];
                float bh[2] = {f.x, f.z};
                float bl[2] = {f.y, f.w};
                mma8(sfr[ni], qh[ks], bh);
                mma8(sfr[ni], qh[ks], bl);
                mma8(sfr[ni], ql[ks], bh);
            }
        }
        // ---- online softmax ----
        float t0=-INFINITY, t1=-INFINITY;
        #pragma unroll
        for (int ni=0;ni<8;ni++){
            t0 = fmaxf(t0, fmaxf(sfr[ni][0], sfr[ni][1]));
            t1 = fmaxf(t1, fmaxf(sfr[ni][2], sfr[ni][3]));
        }
        t0 = fmaxf(t0, __shfl_xor_sync(0xffffffffu, t0, 1));
        t0 = fmaxf(t0, __shfl_xor_sync(0xffffffffu, t0, 2));
        t1 = fmaxf(t1, __shfl_xor_sync(0xffffffffu, t1, 1));
        t1 = fmaxf(t1, __shfl_xor_sync(0xffffffffu, t1, 2));
        float mn0 = fmaxf(m0, t0), mn1 = fmaxf(m1, t1);
        float a0 = __expf(m0 - mn0), a1 = __expf(m1 - mn1);
        float p0 = 0.f, p1 = 0.f;
        #pragma unroll
        for (int ni=0;ni<8;ni++){
            sfr[ni][0] = __expf(sfr[ni][0]-mn0); p0 += sfr[ni][0];
            sfr[ni][1] = __expf(sfr[ni][1]-mn0); p0 += sfr[ni][1];
            sfr[ni][2] = __expf(sfr[ni][2]-mn1); p1 += sfr[ni][2];
            sfr[ni][3] = __expf(sfr[ni][3]-mn1); p1 += sfr[ni][3];
        }
        p0 += __shfl_xor_sync(0xffffffffu, p0, 1);
        p0 += __shfl_xor_sync(0xffffffffu, p0, 2);
        p1 += __shfl_xor_sync(0xffffffffu, p1, 1);
        p1 += __shfl_xor_sync(0xffffffffu, p1, 2);
        l0 = l0*a0 + p0; l1 = l1*a1 + p1;
        m0 = mn0; m1 = mn1;
        // write P in paired layout: idx(c) = ((c&3)<<1) | ((c>>2)&1) within chunk
        {
            int c0 = 2*tg, c1 = 2*tg+1;
            int i0 = ((c0&3)<<1) | ((c0>>2)&1);
            int i1 = ((c1&3)<<1) | ((c1>>2)&1);
            #pragma unroll
            for (int ni=0;ni<8;ni++){
                ofr[ni][0]*=a0; ofr[ni][1]*=a0; ofr[ni][2]*=a1; ofr[ni][3]*=a1;
                Psf[prow*72     + ni*8 + i0] = tf32r(sfr[ni][0]);
                Psf[prow*72     + ni*8 + i1] = tf32r(sfr[ni][1]);
                Psf[(prow+8)*72 + ni*8 + i0] = tf32r(sfr[ni][2]);
                Psf[(prow+8)*72 + ni*8 + i1] = tf32r(sfr[ni][3]);
            }
        }
        __syncwarp();
        // ---- O += P * V ----
        #pragma unroll
        for (int k2=0;k2<8;k2++){
            float2 f0 = *(const float2*)&Psf[prow*72     + k2*8 + tg*2];
            float2 f1 = *(const float2*)&Psf[(prow+8)*72 + k2*8 + tg*2];
            float pa[4] = {f0.x, f1.x, f0.y, f1.y};
            #pragma unroll
            for (int ni=0;ni<8;ni++){
                float bv[2];
                bv[0]=Vs[(k2*8+tg)*68   + ni*8+lg];
                bv[1]=Vs[(k2*8+4+tg)*68 + ni*8+lg];
                mma8(ofr[ni], pa, bv);
            }
        }
        __syncthreads();
    }
    float i0 = 1.f/l0, i1 = 1.f/l1;
    int r0 = qt*128 + w*16 + lg;
    float* o0 = g_AO + ((size_t)b*NS + r0)*ND + h*64;
    float* o1 = o0 + (size_t)8*ND;
    #pragma unroll
    for (int ni=0;ni<8;ni++){
        int col = ni*8 + 2*tg;
        o0[col]   = ofr[ni][0]*i0;
        o0[col+1] = ofr[ni][1]*i0;
        o1[col]   = ofr[ni][2]*i1;
        o1[col+1] = ofr[ni][3]*i1;
    }
}

// ---------------------------------------------------------------------------
// Kernel 3: output projection out = AO @ wo^T (plain tf32, paired float2 smem)
// ---------------------------------------------------------------------------
__global__ __launch_bounds__(128) void oproj_kernel(
    const float* __restrict__ wo, float* __restrict__ out)
{
    __shared__ float2 Ap2[64*20];
    __shared__ float2 Bp2[64*20];

    const int tid = threadIdx.x;
    const int lane = tid & 31, warp = tid >> 5;
    const int wm = warp >> 1, wn = warp & 1;
    const int lg = lane >> 2, tg = lane & 3;
    const int s_ = tid & 3, ch_ = (tid >> 2) & 3, r0_ = tid >> 4;

    const int tok0 = blockIdx.x * 64;
    const int n0 = blockIdx.y * 64;
    const float* Xb = g_AO + (size_t)tok0 * ND;
    const float* Wb = wo + (size_t)n0 * ND;

    float c[2][4][4];
    #pragma unroll
    for (int mi=0;mi<2;mi++)
      #pragma unroll
      for (int ni=0;ni<4;ni++)
        #pragma unroll
        for (int q=0;q<4;q++) c[mi][ni][q]=0.f;

    for (int kt = 0; kt < ND/32; ++kt){
        const int k0 = kt * 32;
        __syncthreads();
        const float* Xa = Xb + k0 + ch_*8 + s_;
        const float* Wa = Wb + k0 + ch_*8 + s_;
        #pragma unroll
        for (int rr=0; rr<8; rr++){
            int row = rr*8 + r0_;
            Ap2[row*20 + ch_*4 + s_] =
                make_float2(tf32r(Xa[(size_t)row*ND]), tf32r(Xa[(size_t)row*ND+4]));
            Bp2[row*20 + ch_*4 + s_] =
                make_float2(tf32r(Wa[(size_t)row*ND]), tf32r(Wa[(size_t)row*ND+4]));
        }
        __syncthreads();
        #pragma unroll
        for (int ks=0;ks<4;ks++){
            float a[2][4], bfr[4][2];
            #pragma unroll
            for (int mi=0;mi<2;mi++){
                int rb = wm*32 + mi*16;
                float2 f0 = Ap2[(rb+lg)*20 + ks*4 + tg];
                float2 f1 = Ap2[(rb+8+lg)*20 + ks*4 + tg];
                a[mi][0]=f0.x; a[mi][1]=f1.x; a[mi][2]=f0.y; a[mi][3]=f1.y;
            }
            #pragma unroll
            for (int ni=0;ni<4;ni++){
                int n2 = wn*32 + ni*8;
                float2 f = Bp2[(n2+lg)*20 + ks*4 + tg];
                bfr[ni][0]=f.x; bfr[ni][1]=f.y;
            }
            #pragma unroll
            for (int mi=0;mi<2;mi++)
              #pragma unroll
              for (int ni=0;ni<4;ni++)
                mma8(c[mi][ni], a[mi], bfr[ni]);
        }
    }
    #pragma unroll
    for (int mi=0;mi<2;mi++)
      #pragma unroll
      for (int ni=0;ni<4;ni++){
        int row = tok0 + wm*32 + mi*16 + lg;
        int col = n0 + wn*32 + ni*8 + 2*tg;
        float* p0 = out + (size_t)row*ND + col;
        float* p1 = out + (size_t)(row+8)*ND + col;
        p0[0] = c[mi][ni][0]; p0[1] = c[mi][ni][1];
        p1[0] = c[mi][ni][2]; p1[1] = c[mi][ni][3];
      }
}

// ---------------------------------------------------------------------------
extern "C" void kernel_launch(void* const* d_in, const int* in_sizes, int n_in,
                              void* d_out, int out_size)
{
    (void)in_sizes; (void)n_in; (void)out_size;
    const float* X    = (const float*)d_in[0];
    const float* cosp = (const float*)d_in[1];
    const float* sinp = (const float*)d_in[2];
    // d_in[3] = position_ids (unused by reference)
    const float* wq   = (const float*)d_in[4];
    const float* wk   = (const float*)d_in[5];
    const float* wv   = (const float*)d_in[6];
    const float* wo   = (const float*)d_in[7];
    const float* qsc  = (const float*)d_in[8];
    const float* ksc  = (const float*)d_in[9];
    float* out = (float*)d_out;

    cudaFuncSetAttribute(attn_kernel,
                         cudaFuncAttributeMaxDynamicSharedMemorySize, ATTN_SMEM);

    qkv_kernel<<<dim3(NTOK/64, 48), 128>>>(X, wq, wk, wv, cosp, sinp, qsc, ksc);
    attn_kernel<<<dim3(NS/128, NH, NB), 256, ATTN_SMEM>>>();
    oproj_kernel<<<dim3(NTOK/64, ND/64), 128>>>(wo, out);
}

// round 5
// speedup vs baseline: 1.9338x; 1.9338x over previous
#include <cuda_runtime.h>
#include <cuda_bf16.h>
#include <math.h>
#include <stdint.h>

#define NB 4
#define NS 2048
#define ND 1024
#define NH 16
#define NHD 64
#define NTOK (NB*NS)

// ---------------- device global scratch (allocation-free) ----------------
// packed unit = 16B = {hi pair_t, hi pair_{t+4}, lo pair_t, lo pair_{t+4}}
// (pair_j = bf16x2 of elements 2j,2j+1 within a k16 chunk)
__device__ uint4 g_Xp [(size_t)NTOK*64*4];        // X packed   [row][chunk64][unit4]
__device__ uint4 g_Wp [(size_t)3*ND*64*4];        // wq|wk|wv packed rows 0..3071
__device__ uint4 g_WOp[(size_t)ND*64*4];          // wo packed
__device__ uint4 g_Qp [(size_t)NB*NH*NS*16];      // Q packed   [bh row][chunk4][unit4]
__device__ uint4 g_Kp [(size_t)NB*NH*NS*16];      // K packed
__device__ float g_V  [(size_t)NB*NH*NS*NHD];     // V fp32 (tf32-rounded)
__device__ uint4 g_AOp[(size_t)NTOK*64*4];        // attention out packed

// ---------------- helpers ----------------
__device__ __forceinline__ uint32_t smem_u32(const void* p){
    uint32_t a;
    asm("{ .reg .u64 t; cvta.to.shared.u64 t, %1; cvt.u32.u64 %0, t; }" : "=r"(a) : "l"(p));
    return a;
}
__device__ __forceinline__ float tf32r(float x){
    uint32_t y; asm("cvt.rna.tf32.f32 %0, %1;" : "=r"(y) : "f"(x));
    return __uint_as_float(y);
}
__device__ __forceinline__ void mma8(float c[4], const float a[4], const float b[2]){
    asm volatile(
      "mma.sync.aligned.m16n8k8.row.col.f32.tf32.tf32.f32 "
      "{%0,%1,%2,%3}, {%4,%5,%6,%7}, {%8,%9}, {%0,%1,%2,%3};\n"
      : "+f"(c[0]),"+f"(c[1]),"+f"(c[2]),"+f"(c[3])
      : "r"(__float_as_uint(a[0])),"r"(__float_as_uint(a[1])),
        "r"(__float_as_uint(a[2])),"r"(__float_as_uint(a[3])),
        "r"(__float_as_uint(b[0])),"r"(__float_as_uint(b[1])));
}
__device__ __forceinline__ void mmabf(float c[4], const uint32_t a[4], const uint32_t b[2]){
    asm volatile(
      "mma.sync.aligned.m16n8k16.row.col.f32.bf16.bf16.f32 "
      "{%0,%1,%2,%3}, {%4,%5,%6,%7}, {%8,%9}, {%0,%1,%2,%3};\n"
      : "+f"(c[0]),"+f"(c[1]),"+f"(c[2]),"+f"(c[3])
      : "r"(a[0]),"r"(a[1]),"r"(a[2]),"r"(a[3]), "r"(b[0]),"r"(b[1]));
}
__device__ __forceinline__ void cpa16(uint32_t saddr, const void* gaddr){
    asm volatile("cp.async.cg.shared.global [%0], [%1], 16;" :: "r"(saddr), "l"(gaddr) : "memory");
}
#define CP_COMMIT() asm volatile("cp.async.commit_group;" ::: "memory")
#define CP_WAIT(n)  asm volatile("cp.async.wait_group %0;" :: "n"(n) : "memory")

__device__ __forceinline__ uint32_t packbf2(__nv_bfloat16 a, __nv_bfloat16 b){
    return (uint32_t)__bfloat16_as_ushort(a) | ((uint32_t)__bfloat16_as_ushort(b) << 16);
}
__device__ __forceinline__ void bfsplit2(float a, float b, uint32_t& hi, uint32_t& lo){
    __nv_bfloat16 ha = __float2bfloat16(a), hb = __float2bfloat16(b);
    hi = packbf2(ha, hb);
    lo = packbf2(__float2bfloat16(a - __bfloat162float(ha)),
                 __float2bfloat16(b - __bfloat162float(hb)));
}

// ---------------------------------------------------------------------------
// prep: one thread packs one k16 chunk (16 floats -> 4 units of 16B)
// ---------------------------------------------------------------------------
__device__ __forceinline__ void pack_chunk(const float* src, uint4* dst){
    float x[16];
    #pragma unroll
    for (int i=0;i<4;i++){ float4 v = *(const float4*)(src + i*4);
        x[i*4]=v.x; x[i*4+1]=v.y; x[i*4+2]=v.z; x[i*4+3]=v.w; }
    uint32_t hi[8], lo[8];
    #pragma unroll
    for (int j=0;j<8;j++) bfsplit2(x[2*j], x[2*j+1], hi[j], lo[j]);
    #pragma unroll
    for (int u=0;u<4;u++) dst[u] = make_uint4(hi[u], hi[u+4], lo[u], lo[u+4]);
}

__global__ __launch_bounds__(256) void prep_x(const float* __restrict__ X){
    int i = blockIdx.x*256 + threadIdx.x;       // chunk id, exact grid
    pack_chunk(X + (size_t)i*16, g_Xp + (size_t)i*4);
}

__global__ __launch_bounds__(256) void prep_w(
    const float* __restrict__ wq, const float* __restrict__ wk,
    const float* __restrict__ wv, const float* __restrict__ wo){
    int i = blockIdx.x*256 + threadIdx.x;       // 0..262143
    if (i < 3*ND*64){
        int row = i >> 6, c = i & 63;
        int which = row >> 10, r = row & 1023;
        const float* src = (which==0)? wq : (which==1)? wk : wv;
        pack_chunk(src + (size_t)r*ND + c*16, g_Wp + (size_t)i*4);
    } else {
        int j = i - 3*ND*64;
        int row = j >> 6, c = j & 63;
        pack_chunk(wo + (size_t)row*ND + c*16, g_WOp + (size_t)j*4);
    }
}

// ---------------------------------------------------------------------------
// GEMM: C[128x128] = A[128rows x 1024] * B[128rows x 1024]^T, bf16x2 3-term.
// 4 warps, warp tile 64x64. 2-stage cp.async pipeline, k-tile=32 (2 chunks).
// smem row stride 192B (128B data + 64 pad; conflict-free LDS.128 phases).
// mode 0: A=Xp, B=Wp fused; epilogue RMS(+scale)+RoPE -> g_Qp/g_Kp packed, g_V
// mode 1: A=AOp, B=WOp; plain store to out
// ---------------------------------------------------------------------------
#define GEMM_STAGE 49152
#define GEMM_SMEM  (2*GEMM_STAGE)

__global__ __launch_bounds__(128) void gemm128(
    int mode,
    const float* __restrict__ cosp, const float* __restrict__ sinp,
    const float* __restrict__ qsc,  const float* __restrict__ ksc,
    float* __restrict__ outp)
{
    extern __shared__ __align__(16) char dsm[];
    const int tid = threadIdx.x, lane = tid & 31, w = tid >> 5;
    const int lg = lane >> 2, tg = lane & 3;
    const int wm = w >> 1, wn = w & 1;
    const int tok0 = blockIdx.x * 128;
    const int nt = blockIdx.y;
    const int brow0 = nt * 128;
    const uint32_t sdyn = smem_u32(dsm);

    const uint4* Aunits = mode ? g_AOp : g_Xp;
    const uint4* Bunits = mode ? g_WOp : g_Wp;

    float c[4][8][4];
    #pragma unroll
    for (int mi=0;mi<4;mi++)
      #pragma unroll
      for (int ni=0;ni<8;ni++)
        #pragma unroll
        for (int q=0;q<4;q++) c[mi][ni][q]=0.f;

    // issue stage helper (inline)
    #define G_ISSUE(ck, s) do { \
        uint32_t sa = sdyn + (s)*GEMM_STAGE; \
        uint32_t sb = sa + 24576; \
        int ck2 = (ck)*2; \
        _Pragma("unroll") \
        for (int i=0;i<8;i++){ \
            int idx = i*128 + tid; \
            int u = idx&3, ch = (idx>>2)&1, row = idx>>3; \
            cpa16(sa + row*192 + ch*64 + u*16, \
                  Aunits + ((size_t)(tok0+row)*64 + ck2 + ch)*4 + u); \
            cpa16(sb + row*192 + ch*64 + u*16, \
                  Bunits + ((size_t)(brow0+row)*64 + ck2 + ch)*4 + u); \
        } \
        CP_COMMIT(); \
    } while(0)

    G_ISSUE(0, 0);
    for (int ck = 0; ck < 32; ++ck){
        if (ck < 31){ G_ISSUE(ck+1, (ck+1)&1); CP_WAIT(1); }
        else        { CP_WAIT(0); }
        __syncthreads();
        const char* pA = dsm + (ck&1)*GEMM_STAGE;
        const char* pB = pA + 24576;
        #pragma unroll
        for (int ch=0; ch<2; ++ch){
            uint32_t ah[4][4], al[4][4];
            #pragma unroll
            for (int mi=0;mi<4;mi++){
                int r = wm*64 + mi*16 + lg;
                uint4 u0 = *(const uint4*)(pA + r*192 + ch*64 + tg*16);
                uint4 u1 = *(const uint4*)(pA + (r+8)*192 + ch*64 + tg*16);
                ah[mi][0]=u0.x; ah[mi][1]=u1.x; ah[mi][2]=u0.y; ah[mi][3]=u1.y;
                al[mi][0]=u0.z; al[mi][1]=u1.z; al[mi][2]=u0.w; al[mi][3]=u1.w;
            }
            #pragma unroll
            for (int ni=0;ni<8;ni++){
                int r = wn*64 + ni*8 + lg;
                uint4 bu = *(const uint4*)(pB + r*192 + ch*64 + tg*16);
                uint32_t bh[2] = {bu.x, bu.y};
                uint32_t bl[2] = {bu.z, bu.w};
                #pragma unroll
                for (int mi=0;mi<4;mi++){
                    mmabf(c[mi][ni], ah[mi], bh);
                    mmabf(c[mi][ni], ah[mi], bl);
                    mmabf(c[mi][ni], al[mi], bh);
                }
            }
        }
        __syncthreads();
    }
    #undef G_ISSUE

    // ---- epilogue (all in registers; cols of one head live in one warp) ----
    float rs[4][2];
    #pragma unroll
    for (int mi=0;mi<4;mi++){
        float s0=0.f, s1=0.f;
        #pragma unroll
        for (int ni=0;ni<8;ni++){
            s0 += c[mi][ni][0]*c[mi][ni][0] + c[mi][ni][1]*c[mi][ni][1];
            s1 += c[mi][ni][2]*c[mi][ni][2] + c[mi][ni][3]*c[mi][ni][3];
        }
        s0 += __shfl_xor_sync(0xffffffffu, s0, 1);
        s0 += __shfl_xor_sync(0xffffffffu, s0, 2);
        s1 += __shfl_xor_sync(0xffffffffu, s1, 1);
        s1 += __shfl_xor_sync(0xffffffffu, s1, 2);
        rs[mi][0] = rsqrtf(s0*(1.f/64.f) + 1e-6f);
        rs[mi][1] = rsqrtf(s1*(1.f/64.f) + 1e-6f);
    }

    if (mode == 1){
        #pragma unroll
        for (int mi=0;mi<4;mi++)
          #pragma unroll
          for (int half=0; half<2; ++half){
            int token = tok0 + wm*64 + mi*16 + half*8 + lg;
            float* dst = outp + (size_t)token*ND + nt*128 + wn*64;
            #pragma unroll
            for (int ni=0;ni<8;ni++)
                *(float2*)(dst + ni*8 + 2*tg) =
                    make_float2(c[mi][ni][half*2], c[mi][ni][half*2+1]);
          }
        return;
    }

    const int which = nt >> 3;
    const int head = (nt & 7)*2 + wn;

    if (which == 2){
        #pragma unroll
        for (int mi=0;mi<4;mi++)
          #pragma unroll
          for (int half=0; half<2; ++half){
            int token = tok0 + wm*64 + mi*16 + half*8 + lg;
            int bb = token >> 11, ss = token & (NS-1);
            float rms = rs[mi][half];
            float* dst = g_V + ((size_t)((bb*NH + head)*NS + ss))*64;
            #pragma unroll
            for (int ni=0;ni<8;ni++)
                *(float2*)(dst + ni*8 + 2*tg) =
                    make_float2(tf32r(c[mi][ni][half*2]*rms),
                                tf32r(c[mi][ni][half*2+1]*rms));
          }
    } else {
        const float* sc = (which==0)? qsc : ksc;
        float sc2[8][2];
        #pragma unroll
        for (int ni=0;ni<8;ni++){
            float2 s2 = *(const float2*)(sc + ni*8 + 2*tg);
            sc2[ni][0]=s2.x; sc2[ni][1]=s2.y;
        }
        uint4* gdst = (which==0)? g_Qp : g_Kp;
        #pragma unroll
        for (int mi=0;mi<4;mi++)
          #pragma unroll
          for (int half=0; half<2; ++half){
            int token = tok0 + wm*64 + mi*16 + half*8 + lg;
            int bb = token >> 11, ss = token & (NS-1);
            float rms = rs[mi][half];
            float vr[8][2];
            #pragma unroll
            for (int ni=0;ni<8;ni++){
                vr[ni][0] = c[mi][ni][half*2]*rms*sc2[ni][0];
                vr[ni][1] = c[mi][ni][half*2+1]*rms*sc2[ni][1];
            }
            const float* cb = cosp + (size_t)token*64;
            const float* sb = sinp + (size_t)token*64;
            float ov[8][2];
            #pragma unroll
            for (int ni=0;ni<8;ni++){
                float2 cv = *(const float2*)(cb + ni*8 + 2*tg);
                float2 sv = *(const float2*)(sb + ni*8 + 2*tg);
                int par = ni ^ 2;
                float r0 = (ni & 2) ? vr[par][0] : -vr[par][0];
                float r1 = (ni & 2) ? vr[par][1] : -vr[par][1];
                ov[ni][0] = vr[ni][0]*cv.x + r0*sv.x;
                ov[ni][1] = vr[ni][1]*cv.y + r1*sv.y;
            }
            uint4* dst = gdst + ((size_t)((bb*NH + head)*NS + ss))*16;
            #pragma unroll
            for (int cc=0; cc<4; ++cc){
                uint32_t h0,l0,h1,l1;
                bfsplit2(ov[2*cc][0],   ov[2*cc][1],   h0, l0);
                bfsplit2(ov[2*cc+1][0], ov[2*cc+1][1], h1, l1);
                dst[cc*4 + tg] = make_uint4(h0, h1, l0, l1);
            }
          }
    }
}

// ---------------------------------------------------------------------------
// flash attention: 64 q rows/block, 4 warps. QK = bf16x2 k16 (1 LDS.128 -> 3
// mmas), PV = tf32. K packed (stride 320B), V fp32 (stride 288B), both staged
// via 2-stage cp.async pipeline.
// ---------------------------------------------------------------------------
#define AK_STRIDE 320
#define AV_STRIDE 288
#define AK_BYTES  (64*AK_STRIDE)     // 20480
#define AV_BYTES  (64*AV_STRIDE)     // 18432
#define AV_OFF    (2*AK_BYTES)       // 40960
#define APS_OFF   (AV_OFF + 2*AV_BYTES)  // 77824
#define ATTN_SMEM (APS_OFF + 64*72*4)    // 96256

__global__ __launch_bounds__(128) void attn_kernel()
{
    extern __shared__ __align__(16) char dsm[];
    float* Psf = (float*)(dsm + APS_OFF);          // [64][72]

    const int tid = threadIdx.x, lane = tid & 31, w = tid >> 5;
    const int lg = lane >> 2, tg = lane & 3;
    const int qt = blockIdx.x, h = blockIdx.y, b = blockIdx.z;
    const size_t bhrow = (size_t)(b*NH + h)*NS;
    const uint32_t sdyn = smem_u32(dsm);

    // ---- stage Q into Kbuf0, build per-warp frags ----
    {
        size_t qrow0 = bhrow + (size_t)qt*64;
        #pragma unroll
        for (int i=0;i<8;i++){
            int idx = i*128 + tid;
            int u = idx&3, ch = (idx>>2)&3, row = idx>>4;
            cpa16(sdyn + row*AK_STRIDE + ch*64 + u*16,
                  g_Qp + (qrow0 + row)*16 + ch*4 + u);
        }
        CP_COMMIT(); CP_WAIT(0);
        __syncthreads();
    }
    uint32_t qh[4][4], ql[4][4];
    #pragma unroll
    for (int cc=0; cc<4; ++cc){
        int r = w*16 + lg;
        uint4 u0 = *(const uint4*)(dsm + r*AK_STRIDE + cc*64 + tg*16);
        uint4 u1 = *(const uint4*)(dsm + (r+8)*AK_STRIDE + cc*64 + tg*16);
        qh[cc][0]=u0.x; qh[cc][1]=u1.x; qh[cc][2]=u0.y; qh[cc][3]=u1.y;
        ql[cc][0]=u0.z; ql[cc][1]=u1.z; ql[cc][2]=u0.w; ql[cc][3]=u1.w;
    }
    __syncthreads();

    #define A_ISSUE(kt) do { \
        int s = (kt)&1; \
        uint32_t kb = sdyn + s*AK_BYTES; \
        uint32_t vb = sdyn + AV_OFF + s*AV_BYTES; \
        size_t krow0 = bhrow + (size_t)(kt)*64; \
        _Pragma("unroll") \
        for (int i=0;i<8;i++){ \
            int idx = i*128 + tid; \
            { int u = idx&3, ch = (idx>>2)&3, row = idx>>4; \
              cpa16(kb + row*AK_STRIDE + ch*64 + u*16, \
                    g_Kp + (krow0 + row)*16 + ch*4 + u); } \
            { int u = idx&15, row = idx>>4; \
              cpa16(vb + row*AV_STRIDE + u*16, \
                    (const char*)g_V + (krow0 + row)*256 + u*16); } \
        } \
        CP_COMMIT(); \
    } while(0)

    float ofr[8][4];
    #pragma unroll
    for (int ni=0;ni<8;ni++){ ofr[ni][0]=0;ofr[ni][1]=0;ofr[ni][2]=0;ofr[ni][3]=0; }
    float m0=-INFINITY, m1=-INFINITY, l0=0.f, l1=0.f;
    const int prow = w*16 + lg;

    A_ISSUE(0);
    for (int kt=0; kt<NS/64; ++kt){
        if (kt < NS/64 - 1){ A_ISSUE(kt+1); CP_WAIT(1); }
        else               { CP_WAIT(0); }
        __syncthreads();
        const char* kb = dsm + (kt&1)*AK_BYTES;
        const float* Vsf = (const float*)(dsm + AV_OFF + (kt&1)*AV_BYTES);

        // ---- QK^T: bf16x2, 1 LDS.128 -> 3 mmas per (ni, chunk) ----
        float sfr[8][4];
        #pragma unroll
        for (int ni=0;ni<8;ni++){ sfr[ni][0]=0;sfr[ni][1]=0;sfr[ni][2]=0;sfr[ni][3]=0; }
        #pragma unroll
        for (int ni=0;ni<8;ni++){
            int r = ni*8 + lg;
            #pragma unroll
            for (int cc=0; cc<4; ++cc){
                uint4 bu = *(const uint4*)(kb + r*AK_STRIDE + cc*64 + tg*16);
                uint32_t bh[2] = {bu.x, bu.y};
                uint32_t bl[2] = {bu.z, bu.w};
                mmabf(sfr[ni], qh[cc], bh);
                mmabf(sfr[ni], qh[cc], bl);
                mmabf(sfr[ni], ql[cc], bh);
            }
        }
        // ---- online softmax ----
        float t0=-INFINITY, t1=-INFINITY;
        #pragma unroll
        for (int ni=0;ni<8;ni++){
            t0 = fmaxf(t0, fmaxf(sfr[ni][0], sfr[ni][1]));
            t1 = fmaxf(t1, fmaxf(sfr[ni][2], sfr[ni][3]));
        }
        t0 = fmaxf(t0, __shfl_xor_sync(0xffffffffu, t0, 1));
        t0 = fmaxf(t0, __shfl_xor_sync(0xffffffffu, t0, 2));
        t1 = fmaxf(t1, __shfl_xor_sync(0xffffffffu, t1, 1));
        t1 = fmaxf(t1, __shfl_xor_sync(0xffffffffu, t1, 2));
        float mn0 = fmaxf(m0, t0), mn1 = fmaxf(m1, t1);
        float a0 = __expf(m0 - mn0), a1 = __expf(m1 - mn1);
        float p0 = 0.f, p1 = 0.f;
        #pragma unroll
        for (int ni=0;ni<8;ni++){
            sfr[ni][0] = __expf(sfr[ni][0]-mn0); p0 += sfr[ni][0];
            sfr[ni][1] = __expf(sfr[ni][1]-mn0); p0 += sfr[ni][1];
            sfr[ni][2] = __expf(sfr[ni][2]-mn1); p1 += sfr[ni][2];
            sfr[ni][3] = __expf(sfr[ni][3]-mn1); p1 += sfr[ni][3];
        }
        p0 += __shfl_xor_sync(0xffffffffu, p0, 1);
        p0 += __shfl_xor_sync(0xffffffffu, p0, 2);
        p1 += __shfl_xor_sync(0xffffffffu, p1, 1);
        p1 += __shfl_xor_sync(0xffffffffu, p1, 2);
        l0 = l0*a0 + p0; l1 = l1*a1 + p1;
        m0 = mn0; m1 = mn1;
        // P (tf32) in paired layout: logical col c -> slot ((c&3)<<1)|((c>>2)&1)
        {
            int c0 = 2*tg, c1 = 2*tg+1;
            int i0 = ((c0&3)<<1) | ((c0>>2)&1);
            int i1 = ((c1&3)<<1) | ((c1>>2)&1);
            #pragma unroll
            for (int ni=0;ni<8;ni++){
                ofr[ni][0]*=a0; ofr[ni][1]*=a0; ofr[ni][2]*=a1; ofr[ni][3]*=a1;
                Psf[prow*72     + ni*8 + i0] = tf32r(sfr[ni][0]);
                Psf[prow*72     + ni*8 + i1] = tf32r(sfr[ni][1]);
                Psf[(prow+8)*72 + ni*8 + i0] = tf32r(sfr[ni][2]);
                Psf[(prow+8)*72 + ni*8 + i1] = tf32r(sfr[ni][3]);
            }
        }
        __syncwarp();
        // ---- O += P * V (tf32) ----
        #pragma unroll
        for (int k2=0;k2<8;k2++){
            float2 f0 = *(const float2*)&Psf[prow*72     + k2*8 + tg*2];
            float2 f1 = *(const float2*)&Psf[(prow+8)*72 + k2*8 + tg*2];
            float pa[4] = {f0.x, f1.x, f0.y, f1.y};
            #pragma unroll
            for (int ni=0;ni<8;ni++){
                float bv[2];
                bv[0]=Vsf[(k2*8+tg)*72   + ni*8+lg];
                bv[1]=Vsf[(k2*8+4+tg)*72 + ni*8+lg];
                mma8(ofr[ni], pa, bv);
            }
        }
        __syncthreads();
    }
    #undef A_ISSUE

    // ---- epilogue: write AO packed bf16 hi/lo ----
    float i0 = 1.f/l0, i1 = 1.f/l1;
    #pragma unroll
    for (int half=0; half<2; ++half){
        int token = b*NS + qt*64 + w*16 + half*8 + lg;
        float inv = half ? i1 : i0;
        float v[8][2];
        #pragma unroll
        for (int ni=0;ni<8;ni++){
            v[ni][0] = ofr[ni][half*2]*inv;
            v[ni][1] = ofr[ni][half*2+1]*inv;
        }
        uint4* dst = g_AOp + ((size_t)token*64 + h*4)*4;
        #pragma unroll
        for (int cc=0; cc<4; ++cc){
            uint32_t h0,l0w,h1,l1w;
            bfsplit2(v[2*cc][0],   v[2*cc][1],   h0, l0w);
            bfsplit2(v[2*cc+1][0], v[2*cc+1][1], h1, l1w);
            dst[cc*4 + tg] = make_uint4(h0, h1, l0w, l1w);
        }
    }
}

// ---------------------------------------------------------------------------
extern "C" void kernel_launch(void* const* d_in, const int* in_sizes, int n_in,
                              void* d_out, int out_size)
{
    (void)in_sizes; (void)n_in; (void)out_size;
    const float* X    = (const float*)d_in[0];
    const float* cosp = (const float*)d_in[1];
    const float* sinp = (const float*)d_in[2];
    // d_in[3] = position_ids (unused by reference)
    const float* wq   = (const float*)d_in[4];
    const float* wk   = (const float*)d_in[5];
    const float* wv   = (const float*)d_in[6];
    const float* wo   = (const float*)d_in[7];
    const float* qsc  = (const float*)d_in[8];
    const float* ksc  = (const float*)d_in[9];
    float* out = (float*)d_out;

    cudaFuncSetAttribute(gemm128,
                         cudaFuncAttributeMaxDynamicSharedMemorySize, GEMM_SMEM);
    cudaFuncSetAttribute(attn_kernel,
                         cudaFuncAttributeMaxDynamicSharedMemorySize, ATTN_SMEM);

    prep_x<<<NTOK*64/256, 256>>>(X);
    prep_w<<<4*ND*64/256, 256>>>(wq, wk, wv, wo);
    gemm128<<<dim3(NTOK/128, 24), 128, GEMM_SMEM>>>(0, cosp, sinp, qsc, ksc, nullptr);
    attn_kernel<<<dim3(NS/64, NH, NB), 128, ATTN_SMEM>>>();
    gemm128<<<dim3(NTOK/128, ND/128), 128, GEMM_SMEM>>>(1, nullptr, nullptr, nullptr, nullptr, out);
}